// round 16
// baseline (speedup 1.0000x reference)
#include <cuda_runtime.h>
#include <cuda_bf16.h>
#include <cstdint>

#define NN 50000
#define KK 16
#define DD 256
#define LN_EPS 1e-5f

#define NPIECE 4
#define NTILES 391          // ceil(50000/128); pieces: 98,98,98,97
#define NPAD   (NTILES*128) // 50048

// ---------------- device scratch (zero-initialized at load) ----------------
__device__ uint4 g_ah[(size_t)NPAD * 32];
__device__ uint4 g_al[(size_t)NPAD * 32];
__device__ uint4 g_wh[(size_t)256 * 32];
__device__ uint4 g_wl[(size_t)256 * 32];

#define SWZ(off) ((off) ^ (((off) >> 3) & 0x70))

#define PDL_TRIGGER() asm volatile("griddepcontrol.launch_dependents;" ::: "memory")
#define PDL_WAIT()    asm volatile("griddepcontrol.wait;" ::: "memory")

__device__ __forceinline__ uint32_t smem_to_u32(const void* p) {
    uint32_t a;
    asm("{ .reg .u64 t; cvta.to.shared.u64 t, %1; cvt.u32.u64 %0, t; }" : "=r"(a) : "l"(p));
    return a;
}
__device__ __forceinline__ void ldsm_x4(uint32_t addr, uint32_t* r) {
    asm volatile("ldmatrix.sync.aligned.m8n8.x4.shared.b16 {%0,%1,%2,%3}, [%4];"
                 : "=r"(r[0]), "=r"(r[1]), "=r"(r[2]), "=r"(r[3]) : "r"(addr));
}
__device__ __forceinline__ void mma16816(float* c, const uint32_t* a, uint32_t b0, uint32_t b1) {
    asm volatile("mma.sync.aligned.m16n8k16.row.col.f32.bf16.bf16.f32 "
                 "{%0,%1,%2,%3}, {%4,%5,%6,%7}, {%8,%9}, {%0,%1,%2,%3};"
                 : "+f"(c[0]), "+f"(c[1]), "+f"(c[2]), "+f"(c[3])
                 : "r"(a[0]), "r"(a[1]), "r"(a[2]), "r"(a[3]), "r"(b0), "r"(b1));
}
__device__ __forceinline__ void cpasync16(uint32_t dst, const void* src) {
    asm volatile("cp.async.cg.shared.global [%0], [%1], 16;" :: "r"(dst), "l"(src));
}
#define CP_COMMIT() asm volatile("cp.async.commit_group;" ::: "memory")
#define CP_WAIT(n)  asm volatile("cp.async.wait_group %0;" :: "n"(n) : "memory")

__device__ __forceinline__ void split2(float v0, float v1, unsigned& hi, unsigned& lo) {
    __nv_bfloat16 h0 = __float2bfloat16_rn(v0);
    __nv_bfloat16 h1 = __float2bfloat16_rn(v1);
    __nv_bfloat16 l0 = __float2bfloat16_rn(v0 - __bfloat162float(h0));
    __nv_bfloat16 l1 = __float2bfloat16_rn(v1 - __bfloat162float(h1));
    hi = ((unsigned)__bfloat16_as_ushort(h1) << 16) | (unsigned)__bfloat16_as_ushort(h0);
    lo = ((unsigned)__bfloat16_as_ushort(l1) << 16) | (unsigned)__bfloat16_as_ushort(l0);
}

// ---------------------------------------------------------------------------
// Gather piece: nodes [n0, n1) -> split bf16 z. 1 warp/node. do_wprep on
// piece 0 also splits/transposes W. Ends with PDL trigger (data ready).
// ---------------------------------------------------------------------------
__global__ void __launch_bounds__(256) gather_kernel(
    const float* __restrict__ feats,
    const int*   __restrict__ nbr,
    const float* __restrict__ iw,
    const float* __restrict__ W,
    int n0, int n1, int do_wprep)
{
    if (do_wprep && blockIdx.x < 256) {
        int idx = blockIdx.x * 256 + threadIdx.x;   // idx = n*256 + k
        int n = idx >> 8, k = idx & 255;
        float v = W[(size_t)k * 256 + n];
        __nv_bfloat16 h = __float2bfloat16_rn(v);
        __nv_bfloat16 l = __float2bfloat16_rn(v - __bfloat162float(h));
        reinterpret_cast<unsigned short*>(g_wh)[idx] = __bfloat16_as_ushort(h);
        reinterpret_cast<unsigned short*>(g_wl)[idx] = __bfloat16_as_ushort(l);
    }

    int warp = n0 + blockIdx.x * (blockDim.x >> 5) + (threadIdx.x >> 5);
    int lane = threadIdx.x & 31;

    if (warp < n1) {
        float w = 0.0f;
        int idx = 0;
        if (lane < KK) {
            w   = iw[warp * KK + lane];
            idx = nbr[warp * KK + lane];
        }
        float wsum = w;
        #pragma unroll
        for (int o = 16; o >= 1; o >>= 1)
            wsum += __shfl_xor_sync(0xffffffffu, wsum, o);
        float weff = (wsum == 0.0f) ? (1.0f / KK) : (w / wsum);

        float4 a0 = make_float4(0.f, 0.f, 0.f, 0.f);
        float4 a1 = make_float4(0.f, 0.f, 0.f, 0.f);

        #pragma unroll
        for (int k = 0; k < KK; k++) {
            float wk = __shfl_sync(0xffffffffu, weff, k);
            int   nk = __shfl_sync(0xffffffffu, idx,  k);
            const float4* rp = reinterpret_cast<const float4*>(feats + (size_t)nk * DD);
            float4 f0 = __ldg(rp + lane);
            float4 f1 = __ldg(rp + lane + 32);
            a0.x += wk * f0.x; a0.y += wk * f0.y; a0.z += wk * f0.z; a0.w += wk * f0.w;
            a1.x += wk * f1.x; a1.y += wk * f1.y; a1.z += wk * f1.z; a1.w += wk * f1.w;
        }

        uint2* ah = reinterpret_cast<uint2*>(g_ah) + (size_t)warp * 64;
        uint2* al = reinterpret_cast<uint2*>(g_al) + (size_t)warp * 64;
        uint2 h, l;
        split2(a0.x, a0.y, h.x, l.x); split2(a0.z, a0.w, h.y, l.y);
        ah[lane] = h;  al[lane] = l;
        split2(a1.x, a1.y, h.x, l.x); split2(a1.z, a1.w, h.y, l.y);
        ah[32 + lane] = h;  al[32 + lane] = l;
    }

    PDL_TRIGGER();   // my stores are done -> dependent GEMM piece may launch
}

// ---------------------------------------------------------------------------
// GEMM piece: tiles [tile0, tile0+n). HMMA 3-term split + fused LN.
// Block 128x256, 512 thr = 4x4 warps, warp tile 32x64, cp.async 2-stage.
// PDL: triggers at entry (releases next gather piece to overlap), waits
// before touching gather output.
// ---------------------------------------------------------------------------
#define STG      98304                 // stage: AH 16K | AL 16K | BH 32K | BL 32K
#define SOF_AL   16384
#define SOF_BH   32768
#define SOF_BL   65536
#define SMO_CONST (2 * STG)            // 196608: bias/gamma/beta 3 x 1KB
#define SMEM_TOTAL (SMO_CONST + 3072)  // 199680 B

__global__ void __launch_bounds__(512) gemm_tc_kernel(
    const float* __restrict__ bias,
    const float* __restrict__ gamma,
    const float* __restrict__ beta,
    float* __restrict__ out,
    int tile0)
{
    // Release the next gather piece immediately: it does not consume our data.
    PDL_TRIGGER();

    extern __shared__ char smem[];
    const uint32_t sb = smem_to_u32(smem);
    const int tid  = threadIdx.x;
    const int wid  = tid >> 5;
    const int lane = tid & 31;
    const int wm   = wid >> 2;
    const int wn   = wid & 3;
    const int row0 = (tile0 + blockIdx.x) * 128;

    // dependency-free prologue work
    float* sC = reinterpret_cast<float*>(smem + SMO_CONST);
    if (tid < 256) {
        sC[tid]       = bias[tid];
        sC[256 + tid] = gamma[tid];
        sC[512 + tid] = beta[tid];
    }

    const int ldr = tid >> 3;
    const int ldq = tid & 7;

    auto load_chunk = [&](int ch, int stg) {
        const uint32_t base = sb + stg * STG;
        #pragma unroll
        for (int i = 0; i < 2; i++) {
            int r = ldr + i * 64;
            uint32_t so = SWZ((uint32_t)(r * 128 + ldq * 16));
            size_t gi = (size_t)(row0 + r) * 32 + ch * 8 + ldq;
            cpasync16(base + so,          &g_ah[gi]);
            cpasync16(base + SOF_AL + so, &g_al[gi]);
        }
        #pragma unroll
        for (int i = 0; i < 4; i++) {
            int r = ldr + i * 64;
            uint32_t so = SWZ((uint32_t)(r * 128 + ldq * 16));
            size_t gi = (size_t)r * 32 + ch * 8 + ldq;
            cpasync16(base + SOF_BH + so, &g_wh[gi]);
            cpasync16(base + SOF_BL + so, &g_wl[gi]);
        }
        CP_COMMIT();
    };

    float c[2][8][4];
    #pragma unroll
    for (int i = 0; i < 2; i++)
        #pragma unroll
        for (int j = 0; j < 8; j++)
            #pragma unroll
            for (int q = 0; q < 4; q++) c[i][j][q] = 0.f;

    const int lrow = lane & 15;
    const int lkb  = (lane >> 4) * 16;

    // wait for the producing gather piece before reading g_ah/g_al/g_wh/g_wl
    PDL_WAIT();

    load_chunk(0, 0);

    #pragma unroll
    for (int ch = 0; ch < 4; ch++) {
        if (ch + 1 < 4) load_chunk(ch + 1, (ch + 1) & 1);
        if (ch + 1 < 4) { CP_WAIT(1); } else { CP_WAIT(0); }
        __syncthreads();

        const uint32_t base = sb + (ch & 1) * STG;
        #pragma unroll
        for (int ks = 0; ks < 4; ks++) {
            const int kb = ks * 32 + lkb;
            uint32_t ah[2][4], al[2][4];
            #pragma unroll
            for (int mm = 0; mm < 2; mm++) {
                uint32_t off = SWZ((uint32_t)((wm * 32 + mm * 16 + lrow) * 128 + kb));
                ldsm_x4(base + off, ah[mm]);
                ldsm_x4(base + SOF_AL + off, al[mm]);
            }
            #pragma unroll
            for (int np = 0; np < 4; np++) {
                uint32_t off = SWZ((uint32_t)((wn * 64 + np * 16 + lrow) * 128 + kb));
                uint32_t bh[4], bl[4];
                ldsm_x4(base + SOF_BH + off, bh);
                ldsm_x4(base + SOF_BL + off, bl);
                // term-outer order: consecutive MMAs hit different accumulators
                #pragma unroll
                for (int t = 0; t < 3; t++) {
                    #pragma unroll
                    for (int sub = 0; sub < 2; sub++) {
                        int mn = np * 2 + sub;
                        #pragma unroll
                        for (int mm = 0; mm < 2; mm++) {
                            if (t == 0)      mma16816(c[mm][mn], ah[mm], bh[sub], bh[2 + sub]);
                            else if (t == 1) mma16816(c[mm][mn], ah[mm], bl[sub], bl[2 + sub]);
                            else             mma16816(c[mm][mn], al[mm], bh[sub], bh[2 + sub]);
                        }
                    }
                }
            }
        }
        __syncthreads();
    }

    // ---- +bias, fused LayerNorm ----
    const int q2 = 2 * (lane & 3);
    #pragma unroll
    for (int mm = 0; mm < 2; mm++)
        #pragma unroll
        for (int mn = 0; mn < 8; mn++) {
            int col = wn * 64 + mn * 8 + q2;
            float b0 = sC[col], b1 = sC[col + 1];
            c[mm][mn][0] += b0; c[mm][mn][1] += b1;
            c[mm][mn][2] += b0; c[mm][mn][3] += b1;
        }

    float2* psum  = reinterpret_cast<float2*>(smem);          // [wn*128 + row]
    float2* stats = reinterpret_cast<float2*>(smem + 4096);   // [row]

    #pragma unroll
    for (int mm = 0; mm < 2; mm++) {
        #pragma unroll
        for (int h = 0; h < 2; h++) {
            float s = 0.f, s2 = 0.f;
            #pragma unroll
            for (int mn = 0; mn < 8; mn++) {
                float v0 = c[mm][mn][h * 2 + 0];
                float v1 = c[mm][mn][h * 2 + 1];
                s += v0 + v1;  s2 += v0 * v0 + v1 * v1;
            }
            s  += __shfl_xor_sync(0xffffffffu, s, 1);
            s  += __shfl_xor_sync(0xffffffffu, s, 2);
            s2 += __shfl_xor_sync(0xffffffffu, s2, 1);
            s2 += __shfl_xor_sync(0xffffffffu, s2, 2);
            if ((lane & 3) == 0) {
                int row = wm * 32 + mm * 16 + h * 8 + (lane >> 2);
                psum[wn * 128 + row] = make_float2(s, s2);
            }
        }
    }
    __syncthreads();

    if (tid < 128) {
        float s = 0.f, s2 = 0.f;
        #pragma unroll
        for (int p = 0; p < 4; p++) {
            float2 v = psum[p * 128 + tid];
            s += v.x;  s2 += v.y;
        }
        float mean = s * (1.0f / 256.0f);
        float var  = s2 * (1.0f / 256.0f) - mean * mean;
        stats[tid] = make_float2(mean, rsqrtf(var + LN_EPS));
    }
    __syncthreads();

    #pragma unroll
    for (int mm = 0; mm < 2; mm++)
        #pragma unroll
        for (int h = 0; h < 2; h++) {
            int row  = wm * 32 + mm * 16 + h * 8 + (lane >> 2);
            int grow = row0 + row;
            if (grow >= NN) continue;
            float2 st = stats[row];
            #pragma unroll
            for (int mn = 0; mn < 8; mn++) {
                int col = wn * 64 + mn * 8 + q2;
                float v0 = (c[mm][mn][h * 2 + 0] - st.x) * st.y * sC[256 + col]     + sC[512 + col];
                float v1 = (c[mm][mn][h * 2 + 1] - st.x) * st.y * sC[256 + col + 1] + sC[512 + col + 1];
                *reinterpret_cast<float2*>(out + (size_t)grow * DD + col) = make_float2(v0, v1);
            }
        }
}

// ---------------------------------------------------------------------------
// PDL-chained launch on ONE stream (no stream/event creation -> no allocs).
// g0(plain) -> gm0(PDL) -> g1(PDL) -> gm1(PDL) -> ... -> gm3(PDL).
// gm_p triggers at entry so g_{p+1} overlaps it; g_p triggers after stores so
// gm_p's wait sees the data. g0 is a plain launch so each graph replay fully
// joins on the previous replay before g_ah is overwritten.
// ---------------------------------------------------------------------------
static void launch_pdl(const void* fn, dim3 grid, dim3 block, size_t smem,
                       void** args, int use_pdl)
{
    cudaLaunchConfig_t cfg = {};
    cfg.gridDim = grid;
    cfg.blockDim = block;
    cfg.dynamicSmemBytes = smem;
    cfg.stream = 0;
    cudaLaunchAttribute attr[1];
    if (use_pdl) {
        attr[0].id = cudaLaunchAttributeProgrammaticStreamSerialization;
        attr[0].val.programmaticStreamSerializationAllowed = 1;
        cfg.attrs = attr;
        cfg.numAttrs = 1;
    }
    cudaLaunchKernelExC(&cfg, fn, args);
}

extern "C" void kernel_launch(void* const* d_in, const int* in_sizes, int n_in,
                              void* d_out, int out_size)
{
    const float* feats = (const float*)d_in[0];
    const int*   nbr   = (const int*)d_in[1];    // int32 (JAX x64 disabled)
    const float* iw    = (const float*)d_in[2];
    const float* Wm    = (const float*)d_in[3];
    const float* bias  = (const float*)d_in[4];
    const float* gamma = (const float*)d_in[5];
    const float* beta  = (const float*)d_in[6];
    float*       out   = (float*)d_out;

    static const int tiles_per[NPIECE] = {98, 98, 98, 97};

    cudaFuncSetAttribute(gemm_tc_kernel,
                         cudaFuncAttributeMaxDynamicSharedMemorySize, SMEM_TOTAL);

    int tile0 = 0;
    for (int p = 0; p < NPIECE; p++) {
        int n0 = tile0 * 128;
        int n1 = (p == NPIECE - 1) ? NN : (tile0 + tiles_per[p]) * 128;
        int nwarps = n1 - n0;
        int gctas  = (nwarps + 7) / 8;
        int wprep  = (p == 0) ? 1 : 0;

        void* gargs[] = {(void*)&feats, (void*)&nbr, (void*)&iw, (void*)&Wm,
                         (void*)&n0, (void*)&n1, (void*)&wprep};
        launch_pdl((const void*)gather_kernel, dim3(gctas), dim3(256), 0,
                   gargs, p == 0 ? 0 : 1);

        void* margs[] = {(void*)&bias, (void*)&gamma, (void*)&beta,
                         (void*)&out, (void*)&tile0};
        launch_pdl((const void*)gemm_tc_kernel, dim3(tiles_per[p]), dim3(512),
                   SMEM_TOTAL, margs, 1);

        tile0 += tiles_per[p];
    }
}